// round 1
// baseline (speedup 1.0000x reference)
#include <cuda_runtime.h>
#include <cuda_bf16.h>

// Problem constants (from reference): D=272 feature dim, NC=19 classes.
constexpr int D   = 272;   // floats per capsule row
constexpr int D4  = 68;    // float4 per row
constexpr int NC  = 19;    // output classes
constexpr int NT  = 272;   // threads per block: 4 groups x 68 float4-lanes

__global__ __launch_bounds__(NT)
void capsule_seg_kernel(const float* __restrict__ feats,   // [B*H*Wd, D]
                        const float* __restrict__ Wm,      // [D, NC]
                        const float* __restrict__ bias,    // [NC]
                        const int*   __restrict__ pidx,    // [P]
                        const int*   __restrict__ seg,     // [P] sorted
                        int P,
                        float* __restrict__ out)           // [NI, NC]
{
    const int s = blockIdx.x;
    const int t = threadIdx.x;
    const int g = t / D4;          // point-phase group 0..3
    const int l = t - g * D4;      // float4 lane within row 0..67

    // Segment bounds via two lower_bounds on the sorted segment_ids.
    // Uniform across the block -> broadcast loads, no divergence.
    int lo = 0, hi = P;
    while (lo < hi) { int m = (lo + hi) >> 1; if (__ldg(seg + m) < s)     lo = m + 1; else hi = m; }
    const int start = lo;
    hi = P;
    while (lo < hi) { int m = (lo + hi) >> 1; if (__ldg(seg + m) < s + 1) lo = m + 1; else hi = m; }
    const int end = lo;

    __shared__ int    sidx[256];
    __shared__ float4 red[NT];
    __shared__ float  shp[D];

    float4 acc = make_float4(0.f, 0.f, 0.f, 0.f);

    for (int base = start; base < end; base += 256) {
        const int n = min(256, end - base);
        if (t < n) sidx[t] = pidx[base + t];
        __syncthreads();
        // Each group g walks points g, g+4, g+8, ... ; each thread loads one
        // aligned float4 (rows are 1088 B = 16B-aligned).
        for (int k = g; k < n; k += 4) {
            const float4* row = reinterpret_cast<const float4*>(feats + (size_t)sidx[k] * D);
            const float4 v = __ldg(row + l);
            acc.x += v.x; acc.y += v.y; acc.z += v.z; acc.w += v.w;
        }
        __syncthreads();
    }

    red[t] = acc;
    __syncthreads();

    const int   count = end - start;
    const float inv   = 1.0f / (float)max(count, 1);

    if (g == 0) {
        const float4 a = red[l];
        const float4 b4 = red[D4 + l];
        const float4 c4 = red[2 * D4 + l];
        const float4 d4 = red[3 * D4 + l];
        float4 p;
        p.x = (a.x + b4.x + c4.x + d4.x) * inv;
        p.y = (a.y + b4.y + c4.y + d4.y) * inv;
        p.z = (a.z + b4.z + c4.z + d4.z) * inv;
        p.w = (a.w + b4.w + c4.w + d4.w) * inv;
        reinterpret_cast<float4*>(shp)[l] = p;
    }
    __syncthreads();

    // Tiny linear head + sigmoid: out[s, c] = sigmoid(b[c] + sum_d shp[d]*W[d,c])
    if (t < NC) {
        float a = __ldg(bias + t);
        #pragma unroll 4
        for (int d = 0; d < D; ++d)
            a += shp[d] * __ldg(Wm + d * NC + t);
        out[(size_t)s * NC + t] = 1.0f / (1.0f + __expf(-a));
    }
}

extern "C" void kernel_launch(void* const* d_in, const int* in_sizes, int n_in,
                              void* d_out, int out_size) {
    const float* feats = (const float*)d_in[0];   // class_capsules [B,H,Wd,D]
    const float* Wm    = (const float*)d_in[1];   // [D, NC]
    const float* bias  = (const float*)d_in[2];   // [NC]
    const int*   pidx  = (const int*)d_in[3];     // [P]
    const int*   seg   = (const int*)d_in[4];     // [P] sorted
    const int    P     = in_sizes[3];
    const int    NI    = out_size / NC;           // 4096

    capsule_seg_kernel<<<NI, NT>>>(feats, Wm, bias, pidx, seg, P, (float*)d_out);
}

// round 2
// speedup vs baseline: 2.1673x; 2.1673x over previous
#include <cuda_runtime.h>
#include <cuda_bf16.h>

constexpr int D    = 272;    // capsule feature dim
constexpr int NC   = 19;     // classes
constexpr int NCP  = 20;     // padded classes (10 f32x2 pairs)
constexpr int MAXROWS = 65536;   // B*H*Wd grid points
constexpr int MAXNI   = 65536;

// Scratch (static __device__ arrays; no allocation)
__device__ __align__(16) float g_proj[MAXROWS * NCP];   // 5.24 MB projected table
__device__ int g_starts[MAXNI + 1];

// ---------------------------------------------------------------------------
// Kernel 1: segment boundaries from sorted segment_ids (O(P) streaming)
// ---------------------------------------------------------------------------
__global__ void bounds_kernel(const int* __restrict__ seg, int P, int NI) {
    int i = blockIdx.x * blockDim.x + threadIdx.x;
    if (i >= P) return;
    int s    = seg[i];
    int prev = (i == 0) ? -1 : seg[i - 1];
    for (int q = prev + 1; q <= s; ++q) g_starts[q] = i;
    if (i == P - 1)
        for (int q = s + 1; q <= NI; ++q) g_starts[q] = P;
}

// ---------------------------------------------------------------------------
// Kernel 2: proj[r, c] = sum_d feats[r, d] * W[d, c]   (c padded to 20)
// 128 threads/block, 256 rows/block (2 rows/thread), packed f32x2 FMA.
// Feats staged through smem in d-chunks of 16 (coalesced gmem, pad-17 smem).
// ---------------------------------------------------------------------------
__global__ __launch_bounds__(128)
void proj_kernel(const float* __restrict__ feats, const float* __restrict__ Wm,
                 int rows) {
    __shared__ float Ws[D * NCP];        // W padded: [d][20], 21760 B
    __shared__ float Fs[256 * 17];       // chunk: 256 rows x 16 d, pad 17

    const int t = threadIdx.x;

    // Stage padded W once
    for (int i = t; i < D * NCP; i += 128) {
        int c = i % NCP, d = i / NCP;
        Ws[i] = (c < NC) ? __ldg(Wm + d * NC + c) : 0.0f;
    }

    const int rowbase = blockIdx.x * 256;

    unsigned long long acc[2][10];
    #pragma unroll
    for (int i = 0; i < 2; ++i)
        #pragma unroll
        for (int c = 0; c < 10; ++c) acc[i][c] = 0ULL;

    for (int dc = 0; dc < D; dc += 16) {
        __syncthreads();   // Fs reuse (and first-iter Ws visibility)
        // Stage: 256 rows x 16 floats = 1024 float4
        #pragma unroll
        for (int i = 0; i < 8; ++i) {
            int fid = i * 128 + t;            // 0..1023
            int r   = fid >> 2, q = fid & 3;  // local row, float4 within chunk
            int gr  = rowbase + r;
            if (gr >= rows) gr = rows - 1;    // clamp (rows divisible in practice)
            float4 v = __ldg(reinterpret_cast<const float4*>(
                                 feats + (size_t)gr * D + dc) + q);
            float* dst = &Fs[r * 17 + q * 4];
            dst[0] = v.x; dst[1] = v.y; dst[2] = v.z; dst[3] = v.w;
        }
        __syncthreads();

        #pragma unroll 4
        for (int dd = 0; dd < 16; ++dd) {
            int d = dc + dd;
            const unsigned long long* wrow =
                reinterpret_cast<const unsigned long long*>(Ws + d * NCP);
            float fa = Fs[t * 17 + dd];
            float fb = Fs[(t + 128) * 17 + dd];
            unsigned long long pa, pb;
            asm("mov.b64 %0, {%1, %1};" : "=l"(pa) : "f"(fa));
            asm("mov.b64 %0, {%1, %1};" : "=l"(pb) : "f"(fb));
            #pragma unroll
            for (int c = 0; c < 10; ++c) {
                unsigned long long w = wrow[c];
                asm("fma.rn.f32x2 %0, %1, %2, %0;" : "+l"(acc[0][c]) : "l"(pa), "l"(w));
                asm("fma.rn.f32x2 %0, %1, %2, %0;" : "+l"(acc[1][c]) : "l"(pb), "l"(w));
            }
        }
    }

    // Write: packed pairs are (class 2c, class 2c+1) -> contiguous in padded row
    int r0 = rowbase + t, r1 = rowbase + t + 128;
    if (r0 < rows) {
        unsigned long long* o = reinterpret_cast<unsigned long long*>(
            g_proj + (size_t)r0 * NCP);
        #pragma unroll
        for (int c = 0; c < 10; ++c) o[c] = acc[0][c];
    }
    if (r1 < rows) {
        unsigned long long* o = reinterpret_cast<unsigned long long*>(
            g_proj + (size_t)r1 * NCP);
        #pragma unroll
        for (int c = 0; c < 10; ++c) o[c] = acc[1][c];
    }
}

// ---------------------------------------------------------------------------
// Kernel 3: per-segment gather-sum of 20-float projections + finalize.
// One block (160 thr = 5 warps) per segment; warp q owns float4 column q.
// ---------------------------------------------------------------------------
__global__ __launch_bounds__(160)
void gather_kernel(const int* __restrict__ pidx,
                   const float* __restrict__ bias,
                   float* __restrict__ out) {
    const int s = blockIdx.x;
    const int t = threadIdx.x;
    const int q = t >> 5;    // warp id: float4 column 0..4
    const int p = t & 31;    // lane: point phase

    const int start = g_starts[s];
    const int end   = g_starts[s + 1];

    const float4* tab = reinterpret_cast<const float4*>(g_proj);
    float4 acc = make_float4(0.f, 0.f, 0.f, 0.f);

    #pragma unroll 4
    for (int k = start + p; k < end; k += 32) {
        int idx  = __ldg(pidx + k);
        float4 v = __ldg(tab + (size_t)idx * 5 + q);
        acc.x += v.x; acc.y += v.y; acc.z += v.z; acc.w += v.w;
    }

    // Warp reduction over the 32 point phases
    #pragma unroll
    for (int off = 16; off > 0; off >>= 1) {
        acc.x += __shfl_down_sync(0xffffffffu, acc.x, off);
        acc.y += __shfl_down_sync(0xffffffffu, acc.y, off);
        acc.z += __shfl_down_sync(0xffffffffu, acc.z, off);
        acc.w += __shfl_down_sync(0xffffffffu, acc.w, off);
    }

    __shared__ float4 sm[5];
    if (p == 0) sm[q] = acc;
    __syncthreads();

    if (t < NC) {
        int count  = end - start;
        float invc = 1.0f / (float)max(count, 1);
        float v = reinterpret_cast<const float*>(sm)[t] * invc + __ldg(bias + t);
        out[(size_t)s * NC + t] = 1.0f / (1.0f + __expf(-v));
    }
}

// ---------------------------------------------------------------------------
extern "C" void kernel_launch(void* const* d_in, const int* in_sizes, int n_in,
                              void* d_out, int out_size) {
    const float* feats = (const float*)d_in[0];   // [B,H,Wd,D]
    const float* Wm    = (const float*)d_in[1];   // [D, NC]
    const float* bias  = (const float*)d_in[2];   // [NC]
    const int*   pidx  = (const int*)d_in[3];     // [P]
    const int*   seg   = (const int*)d_in[4];     // [P] sorted
    const int    P     = in_sizes[3];
    const int    rows  = in_sizes[0] / D;         // 65536
    const int    NI    = out_size / NC;           // 4096

    bounds_kernel<<<(P + 255) / 256, 256>>>(seg, P, NI);
    proj_kernel<<<(rows + 255) / 256, 128>>>(feats, Wm, rows);
    gather_kernel<<<NI, 160>>>(pidx, bias, (float*)d_out);
}